// round 4
// baseline (speedup 1.0000x reference)
#include <cuda_runtime.h>
#include <cuda_bf16.h>
#include <cstddef>

// ---------------- problem constants ----------------
#define BATCH   8
#define EMEM    2
#define BE      16
#define NTOK    512
#define ROWS    (BE*NTOK)   // 8192
#define DIM     768
#define NHEADS  12
#define HDIM    64
#define LAYERS  8
#define DMLP    3072
#define QKVD    2304
#define VIEWS   2

// ---------------- scratch ----------------
__device__ float g_x[ROWS*DIM];
__device__ float g_h[ROWS*DIM];
__device__ float g_qkv[ROWS*QKVD];
__device__ float g_mlp[ROWS*DMLP];
__device__ int   g_vismode;

// ---------------- helpers ----------------
__device__ __forceinline__ float gelu_f(float x) {
    float x3 = x*x*x;
    return 0.5f*x*(1.f + tanhf(0.79788456080286535588f*(x + 0.044715f*x3)));
}

// split two floats into packed bf16x2 (hi) + packed bf16x2 (lo residual)
__device__ __forceinline__ void split2(float x, float y, unsigned &hi, unsigned &lo) {
    __nv_bfloat162 h = __floats2bfloat162_rn(x, y);   // .x low bits
    float rx = x - __bfloat162float(h.x);
    float ry = y - __bfloat162float(h.y);
    __nv_bfloat162 l = __floats2bfloat162_rn(rx, ry);
    hi = *reinterpret_cast<unsigned*>(&h);
    lo = *reinterpret_cast<unsigned*>(&l);
}

__device__ __forceinline__ void mma_bf16(float& c0, float& c1, float& c2, float& c3,
                                         unsigned a0, unsigned a1, unsigned a2, unsigned a3,
                                         unsigned b0, unsigned b1)
{
    asm volatile(
        "mma.sync.aligned.m16n8k16.row.col.f32.bf16.bf16.f32 "
        "{%0,%1,%2,%3},{%4,%5,%6,%7},{%8,%9},{%0,%1,%2,%3};"
        : "+f"(c0), "+f"(c1), "+f"(c2), "+f"(c3)
        : "r"(a0), "r"(a1), "r"(a2), "r"(a3), "r"(b0), "r"(b1));
}

// ---------------- probe dtype of `visible` ----------------
__global__ void probe_visible(const unsigned char* __restrict__ vis) {
    if (threadIdx.x == 0 && blockIdx.x == 0) {
        int nz1 = 0, nz3f = 0;
        for (int i = 0; i < 4096; i++) {
            int m = i & 3;
            if (m == 1 && vis[i]) nz1++;
            if (m == 3 && vis[i]) nz3f++;
        }
        if (nz1 != 0)       g_vismode = 0;
        else if (nz3f != 0) g_vismode = 2;
        else                g_vismode = 1;
    }
}

// ---------------- patch embed + mask + pos + noise bias ----------------
__global__ void embed_kernel(const float* __restrict__ fields,
                             const unsigned char* __restrict__ visible,
                             const float* __restrict__ W_in,
                             const float* __restrict__ mask_emb,
                             const float* __restrict__ pos_emb,
                             const float* __restrict__ noise_b,
                             float* __restrict__ xout)
{
    int row = blockIdx.x;
    int be  = row >> 9;
    int n   = row & 511;
    int b   = be >> 1;
    int h   = n >> 5;
    int w   = n & 31;

    int vi = b*NTOK + n;
    bool vis;
    int mode = g_vismode;
    if (mode == 1)      vis = ((const int*)visible)[vi] != 0;
    else if (mode == 2) vis = ((const float*)visible)[vi] != 0.f;
    else                vis = visible[vi] != 0;

    __shared__ float fv[32];
    if (threadIdx.x < 32) {
        int v = threadIdx.x >> 4;
        int p = (threadIdx.x >> 2) & 3;
        int q = threadIdx.x & 3;
        fv[threadIdx.x] = fields[((size_t)(b*VIEWS + v)*64 + (h*4+p))*128 + (w*4+q)];
    }
    __syncthreads();

    for (int d = threadIdx.x; d < DIM; d += blockDim.x) {
        float acc;
        if (vis) {
            acc = 0.f;
            #pragma unroll
            for (int t = 0; t < 32; t++) acc += fv[t] * W_in[t*DIM + d];
        } else {
            acc = mask_emb[d];
        }
        xout[(size_t)row*DIM + d] = acc + pos_emb[n*DIM + d] + noise_b[d];
    }
}

// ---------------- bf16x3 GEMM: 128x128 block, k-tile 16, 2-stage pipeline ----------------
// C = A@B (+bias)(gelu)(+=C).  flags: bit0 gelu, bit1 accumulate.
__global__ void __launch_bounds__(256) gemm3(
    const float* __restrict__ A, int lda,
    const float* __restrict__ B, int ldb,
    float* __restrict__ C, int ldc,
    int K, const float* __restrict__ bias, int flags)
{
    // packed bf16x2 pairs along k. A: [row][kpair], B: [kpair][col]
    __shared__ unsigned Ahi[2][128][12], Alo[2][128][12];  // stride 12: conflict-free frags
    __shared__ unsigned Bhi[2][8][136],  Blo[2][8][136];   // stride 136 (mod32=8)

    const int tid  = threadIdx.x;
    const int lane = tid & 31;
    const int wid  = tid >> 5;
    const int warpM = (wid >> 2) * 64;
    const int warpN = (wid & 3) * 32;
    const int gid = lane >> 2, tig = lane & 3;
    const int row0 = blockIdx.y * 128, col0 = blockIdx.x * 128;
    const int ktiles = K >> 4;

    float acc[4][4][4] = {};

    float4 ra[2], rb0, rb1;
    const int ar[2] = { (tid        ) >> 2, (tid + 256) >> 2 };
    const int aq[2] = { tid & 3, tid & 3 };
    const int bkp = tid >> 5, bnq = tid & 31;

    auto loadt = [&](int kt) {
        int k0 = kt << 4;
        #pragma unroll
        for (int i = 0; i < 2; i++)
            ra[i] = *(const float4*)&A[(size_t)(row0 + ar[i])*lda + k0 + aq[i]*4];
        rb0 = *(const float4*)&B[(size_t)(k0 + 2*bkp    )*ldb + col0 + bnq*4];
        rb1 = *(const float4*)&B[(size_t)(k0 + 2*bkp + 1)*ldb + col0 + bnq*4];
    };
    auto storet = [&](int st) {
        #pragma unroll
        for (int i = 0; i < 2; i++) {
            unsigned h0,l0,h1,l1;
            split2(ra[i].x, ra[i].y, h0, l0);
            split2(ra[i].z, ra[i].w, h1, l1);
            *(uint2*)&Ahi[st][ar[i]][aq[i]*2] = make_uint2(h0, h1);
            *(uint2*)&Alo[st][ar[i]][aq[i]*2] = make_uint2(l0, l1);
        }
        const float* p0 = (const float*)&rb0;
        const float* p1 = (const float*)&rb1;
        unsigned bh[4], bl[4];
        #pragma unroll
        for (int j = 0; j < 4; j++) split2(p0[j], p1[j], bh[j], bl[j]);
        *(uint4*)&Bhi[st][bkp][bnq*4] = make_uint4(bh[0],bh[1],bh[2],bh[3]);
        *(uint4*)&Blo[st][bkp][bnq*4] = make_uint4(bl[0],bl[1],bl[2],bl[3]);
    };

    loadt(0);
    storet(0);
    __syncthreads();

    for (int kt = 0; kt < ktiles; kt++) {
        int st = kt & 1;
        if (kt + 1 < ktiles) loadt(kt + 1);

        unsigned ah[4][4], al[4][4];
        #pragma unroll
        for (int mi = 0; mi < 4; mi++) {
            int rb_ = warpM + mi*16 + gid;
            ah[mi][0] = Ahi[st][rb_  ][tig];   ah[mi][1] = Ahi[st][rb_+8][tig];
            ah[mi][2] = Ahi[st][rb_  ][tig+4]; ah[mi][3] = Ahi[st][rb_+8][tig+4];
            al[mi][0] = Alo[st][rb_  ][tig];   al[mi][1] = Alo[st][rb_+8][tig];
            al[mi][2] = Alo[st][rb_  ][tig+4]; al[mi][3] = Alo[st][rb_+8][tig+4];
        }
        #pragma unroll
        for (int ni = 0; ni < 4; ni++) {
            int cb = warpN + ni*8 + gid;
            unsigned bh0 = Bhi[st][tig][cb], bh1 = Bhi[st][tig+4][cb];
            unsigned bl0 = Blo[st][tig][cb], bl1 = Blo[st][tig+4][cb];
            #pragma unroll
            for (int mi = 0; mi < 4; mi++) {
                mma_bf16(acc[mi][ni][0], acc[mi][ni][1], acc[mi][ni][2], acc[mi][ni][3],
                         ah[mi][0], ah[mi][1], ah[mi][2], ah[mi][3], bh0, bh1);
                mma_bf16(acc[mi][ni][0], acc[mi][ni][1], acc[mi][ni][2], acc[mi][ni][3],
                         ah[mi][0], ah[mi][1], ah[mi][2], ah[mi][3], bl0, bl1);
                mma_bf16(acc[mi][ni][0], acc[mi][ni][1], acc[mi][ni][2], acc[mi][ni][3],
                         al[mi][0], al[mi][1], al[mi][2], al[mi][3], bh0, bh1);
            }
        }
        if (kt + 1 < ktiles) storet(st ^ 1);
        __syncthreads();
    }

    #pragma unroll
    for (int mi = 0; mi < 4; mi++) {
        #pragma unroll
        for (int ni = 0; ni < 4; ni++) {
            int col = col0 + warpN + ni*8 + tig*2;
            float bia0 = bias ? bias[col]   : 0.f;
            float bia1 = bias ? bias[col+1] : 0.f;
            #pragma unroll
            for (int half = 0; half < 2; half++) {
                int row = row0 + warpM + mi*16 + gid + half*8;
                float v0 = acc[mi][ni][half*2 + 0] + bia0;
                float v1 = acc[mi][ni][half*2 + 1] + bia1;
                if (flags & 1) { v0 = gelu_f(v0); v1 = gelu_f(v1); }
                size_t ci = (size_t)row*ldc + col;
                if (flags & 2) { v0 += C[ci]; v1 += C[ci+1]; }
                C[ci]   = v0;
                C[ci+1] = v1;
            }
        }
    }
}

// ---------------- fused attention, bf16x3 everywhere ----------------
// grid (8 q-tiles, 192 bh), 256 threads. smem:
//   S   [64][516] fp32 scores; after softmax holds packed P: hi at col-pairs [0,256), lo at [256,512)
//   Qh/Ql [64][36] packed pairs along dim
//   KVh/KVl: K as [64][36] (pairs along dim) in pass A; V as [32][72] (pairs along token) in pass B
#define S_STRIDE 516
#define ATTN_SMEM ((64*S_STRIDE + 4*2304) * 4)   // 168960 B
__global__ void __launch_bounds__(256) attn_fused(const float* __restrict__ qkv,
                                                  float* __restrict__ H)
{
    extern __shared__ float fsm[];
    float*    S   = fsm;
    unsigned* Su  = (unsigned*)fsm;
    unsigned* Qh  = (unsigned*)(fsm + 64*S_STRIDE);
    unsigned* Ql  = Qh  + 2304;
    unsigned* KVh = Ql  + 2304;
    unsigned* KVl = KVh + 2304;

    const int bh = blockIdx.y;
    const int qt = blockIdx.x * 64;
    const int be = bh / NHEADS, nh = bh % NHEADS;
    const float* Q  = qkv + (size_t)be*NTOK*QKVD + nh*HDIM;
    const float* Kp = Q + DIM;
    const float* Vv = Q + 2*DIM;

    const int tid = threadIdx.x, lane = tid & 31, wid = tid >> 5;
    const int gid = lane >> 2, tig = lane & 3;
    const int warpM = (wid >> 2) * 32;
    const int warpN = (wid & 3) * 16;

    // stage Q once (hi/lo pairs along dim)
    #pragma unroll
    for (int i = 0; i < 4; i++) {
        int c = tid + i*256;
        int r = c >> 4, q = c & 15;
        float4 v = *(const float4*)&Q[(size_t)(qt+r)*QKVD + q*4];
        unsigned h0,l0,h1,l1;
        split2(v.x, v.y, h0, l0);
        split2(v.z, v.w, h1, l1);
        *(uint2*)&Qh[r*36 + q*2] = make_uint2(h0, h1);
        *(uint2*)&Ql[r*36 + q*2] = make_uint2(l0, l1);
    }

    // ---- pass A: S = scale * Q K^T ----
    for (int kt = 0; kt < 8; kt++) {
        __syncthreads();
        #pragma unroll
        for (int i = 0; i < 4; i++) {
            int c = tid + i*256;
            int r = c >> 4, q = c & 15;
            float4 v = *(const float4*)&Kp[(size_t)(kt*64+r)*QKVD + q*4];
            unsigned h0,l0,h1,l1;
            split2(v.x, v.y, h0, l0);
            split2(v.z, v.w, h1, l1);
            *(uint2*)&KVh[r*36 + q*2] = make_uint2(h0, h1);
            *(uint2*)&KVl[r*36 + q*2] = make_uint2(l0, l1);
        }
        __syncthreads();

        float acc[2][2][4] = {};
        #pragma unroll
        for (int t = 0; t < 4; t++) {
            unsigned ah[2][4], al[2][4];
            #pragma unroll
            for (int mi = 0; mi < 2; mi++) {
                int rb = warpM + mi*16 + gid;
                ah[mi][0] = Qh[ rb   *36 + t*8 + tig];
                ah[mi][1] = Qh[(rb+8)*36 + t*8 + tig];
                ah[mi][2] = Qh[ rb   *36 + t*8 + tig+4];
                ah[mi][3] = Qh[(rb+8)*36 + t*8 + tig+4];
                al[mi][0] = Ql[ rb   *36 + t*8 + tig];
                al[mi][1] = Ql[(rb+8)*36 + t*8 + tig];
                al[mi][2] = Ql[ rb   *36 + t*8 + tig+4];
                al[mi][3] = Ql[(rb+8)*36 + t*8 + tig+4];
            }
            #pragma unroll
            for (int ni = 0; ni < 2; ni++) {
                int cb = warpN + ni*8 + gid;
                unsigned bh0 = KVh[cb*36 + t*8 + tig], bh1 = KVh[cb*36 + t*8 + tig+4];
                unsigned bl0 = KVl[cb*36 + t*8 + tig], bl1 = KVl[cb*36 + t*8 + tig+4];
                #pragma unroll
                for (int mi = 0; mi < 2; mi++) {
                    mma_bf16(acc[mi][ni][0], acc[mi][ni][1], acc[mi][ni][2], acc[mi][ni][3],
                             ah[mi][0], ah[mi][1], ah[mi][2], ah[mi][3], bh0, bh1);
                    mma_bf16(acc[mi][ni][0], acc[mi][ni][1], acc[mi][ni][2], acc[mi][ni][3],
                             ah[mi][0], ah[mi][1], ah[mi][2], ah[mi][3], bl0, bl1);
                    mma_bf16(acc[mi][ni][0], acc[mi][ni][1], acc[mi][ni][2], acc[mi][ni][3],
                             al[mi][0], al[mi][1], al[mi][2], al[mi][3], bh0, bh1);
                }
            }
        }

        const float scale = 0.125f;
        #pragma unroll
        for (int mi = 0; mi < 2; mi++)
            #pragma unroll
            for (int ni = 0; ni < 2; ni++) {
                int col = kt*64 + warpN + ni*8 + tig*2;
                #pragma unroll
                for (int half = 0; half < 2; half++) {
                    int row = warpM + mi*16 + gid + half*8;
                    S[row*S_STRIDE + col]   = acc[mi][ni][half*2+0]*scale;
                    S[row*S_STRIDE + col+1] = acc[mi][ni][half*2+1]*scale;
                }
            }
    }
    __syncthreads();

    // ---- softmax, then pack P as bf16 hi/lo pairs in place ----
    #pragma unroll
    for (int r8 = 0; r8 < 8; r8++) {
        int row = wid*8 + r8;
        float v[16];
        #pragma unroll
        for (int i = 0; i < 4; i++) {
            float4 vv = *(float4*)&S[row*S_STRIDE + lane*16 + i*4];
            v[i*4+0]=vv.x; v[i*4+1]=vv.y; v[i*4+2]=vv.z; v[i*4+3]=vv.w;
        }
        float m = -1e30f;
        #pragma unroll
        for (int i = 0; i < 16; i++) m = fmaxf(m, v[i]);
        #pragma unroll
        for (int off = 16; off > 0; off >>= 1)
            m = fmaxf(m, __shfl_xor_sync(0xffffffffu, m, off));
        float sum = 0.f;
        #pragma unroll
        for (int i = 0; i < 16; i++) { v[i] = __expf(v[i] - m); sum += v[i]; }
        #pragma unroll
        for (int off = 16; off > 0; off >>= 1)
            sum += __shfl_xor_sync(0xffffffffu, sum, off);
        float inv = 1.f / sum;
        unsigned ph[8], pl[8];
        #pragma unroll
        for (int i = 0; i < 8; i++)
            split2(v[2*i]*inv, v[2*i+1]*inv, ph[i], pl[i]);
        *(uint4*)&Su[row*S_STRIDE + lane*8    ]       = make_uint4(ph[0],ph[1],ph[2],ph[3]);
        *(uint4*)&Su[row*S_STRIDE + lane*8 + 4]       = make_uint4(ph[4],ph[5],ph[6],ph[7]);
        *(uint4*)&Su[row*S_STRIDE + 256 + lane*8    ] = make_uint4(pl[0],pl[1],pl[2],pl[3]);
        *(uint4*)&Su[row*S_STRIDE + 256 + lane*8 + 4] = make_uint4(pl[4],pl[5],pl[6],pl[7]);
    }

    // ---- pass B: O = P @ V ----
    float acc[2][2][4] = {};
    for (int kt = 0; kt < 8; kt++) {
        __syncthreads();
        {   // stage V: pairs along token, [32 kpair][72] layout
            int kp = tid >> 3, ng = tid & 7;
            const float* r0 = &Vv[(size_t)(kt*64 + 2*kp    )*QKVD + ng*8];
            const float* r1 = &Vv[(size_t)(kt*64 + 2*kp + 1)*QKVD + ng*8];
            float4 a0 = *(const float4*)r0,      a1 = *(const float4*)(r0+4);
            float4 b0 = *(const float4*)r1,      b1 = *(const float4*)(r1+4);
            unsigned h[8], l[8];
            split2(a0.x, b0.x, h[0], l[0]); split2(a0.y, b0.y, h[1], l[1]);
            split2(a0.z, b0.z, h[2], l[2]); split2(a0.w, b0.w, h[3], l[3]);
            split2(a1.x, b1.x, h[4], l[4]); split2(a1.y, b1.y, h[5], l[5]);
            split2(a1.z, b1.z, h[6], l[6]); split2(a1.w, b1.w, h[7], l[7]);
            *(uint4*)&KVh[kp*72 + ng*8    ] = make_uint4(h[0],h[1],h[2],h[3]);
            *(uint4*)&KVh[kp*72 + ng*8 + 4] = make_uint4(h[4],h[5],h[6],h[7]);
            *(uint4*)&KVl[kp*72 + ng*8    ] = make_uint4(l[0],l[1],l[2],l[3]);
            *(uint4*)&KVl[kp*72 + ng*8 + 4] = make_uint4(l[4],l[5],l[6],l[7]);
        }
        __syncthreads();

        #pragma unroll
        for (int t = 0; t < 4; t++) {
            int kp0 = kt*32 + t*8;
            unsigned ah[2][4], al[2][4];
            #pragma unroll
            for (int mi = 0; mi < 2; mi++) {
                int rb = warpM + mi*16 + gid;
                ah[mi][0] = Su[ rb   *S_STRIDE + kp0 + tig];
                ah[mi][1] = Su[(rb+8)*S_STRIDE + kp0 + tig];
                ah[mi][2] = Su[ rb   *S_STRIDE + kp0 + tig+4];
                ah[mi][3] = Su[(rb+8)*S_STRIDE + kp0 + tig+4];
                al[mi][0] = Su[ rb   *S_STRIDE + 256 + kp0 + tig];
                al[mi][1] = Su[(rb+8)*S_STRIDE + 256 + kp0 + tig];
                al[mi][2] = Su[ rb   *S_STRIDE + 256 + kp0 + tig+4];
                al[mi][3] = Su[(rb+8)*S_STRIDE + 256 + kp0 + tig+4];
            }
            #pragma unroll
            for (int ni = 0; ni < 2; ni++) {
                int cb = warpN + ni*8 + gid;
                unsigned bh0 = KVh[(t*8 + tig  )*72 + cb], bh1 = KVh[(t*8 + tig+4)*72 + cb];
                unsigned bl0 = KVl[(t*8 + tig  )*72 + cb], bl1 = KVl[(t*8 + tig+4)*72 + cb];
                #pragma unroll
                for (int mi = 0; mi < 2; mi++) {
                    mma_bf16(acc[mi][ni][0], acc[mi][ni][1], acc[mi][ni][2], acc[mi][ni][3],
                             ah[mi][0], ah[mi][1], ah[mi][2], ah[mi][3], bh0, bh1);
                    mma_bf16(acc[mi][ni][0], acc[mi][ni][1], acc[mi][ni][2], acc[mi][ni][3],
                             ah[mi][0], ah[mi][1], ah[mi][2], ah[mi][3], bl0, bl1);
                    mma_bf16(acc[mi][ni][0], acc[mi][ni][1], acc[mi][ni][2], acc[mi][ni][3],
                             al[mi][0], al[mi][1], al[mi][2], al[mi][3], bh0, bh1);
                }
            }
        }
    }

    #pragma unroll
    for (int mi = 0; mi < 2; mi++)
        #pragma unroll
        for (int ni = 0; ni < 2; ni++) {
            int col = nh*HDIM + warpN + ni*8 + tig*2;
            #pragma unroll
            for (int half = 0; half < 2; half++) {
                int row = be*NTOK + qt + warpM + mi*16 + gid + half*8;
                H[(size_t)row*DIM + col]   = acc[mi][ni][half*2+0];
                H[(size_t)row*DIM + col+1] = acc[mi][ni][half*2+1];
            }
        }
}

// ---------------- layernorm ----------------
__global__ void ln_kernel(const float* __restrict__ x,
                          const float* __restrict__ s,
                          const float* __restrict__ b,
                          float* __restrict__ h)
{
    int row = blockIdx.x;
    const float* xr = x + (size_t)row*DIM;
    int tid = threadIdx.x;
    float v0 = xr[tid], v1 = xr[tid+256], v2 = xr[tid+512];
    __shared__ float red[256];
    red[tid] = v0 + v1 + v2;
    __syncthreads();
    for (int st = 128; st > 0; st >>= 1) {
        if (tid < st) red[tid] += red[tid+st];
        __syncthreads();
    }
    float mu = red[0] * (1.f/768.f);
    __syncthreads();
    float d0 = v0-mu, d1 = v1-mu, d2 = v2-mu;
    red[tid] = d0*d0 + d1*d1 + d2*d2;
    __syncthreads();
    for (int st = 128; st > 0; st >>= 1) {
        if (tid < st) red[tid] += red[tid+st];
        __syncthreads();
    }
    float rstd = rsqrtf(red[0]*(1.f/768.f) + 1e-5f);
    float* hr = h + (size_t)row*DIM;
    hr[tid]     = d0*rstd*s[tid]     + b[tid];
    hr[tid+256] = d1*rstd*s[tid+256] + b[tid+256];
    hr[tid+512] = d2*rstd*s[tid+512] + b[tid+512];
}

// ---------------- unpatchify ----------------
__global__ void out_kernel(const float* __restrict__ x,
                           const float* __restrict__ W_out,
                           float* __restrict__ out)
{
    int idx = blockIdx.x*blockDim.x + threadIdx.x;
    int e  = idx & 1;
    int Wc = (idx >> 1) & 127;
    int Hc = (idx >> 8) & 63;
    int v  = (idx >> 14) & 1;
    int b  = idx >> 15;
    int h = Hc >> 2, p = Hc & 3, w = Wc >> 2, q = Wc & 3;
    int row = (b*EMEM + e)*NTOK + h*32 + w;
    const float* xr = x + (size_t)row*DIM;
    const float* wr = W_out + ((size_t)v*DIM)*16 + p*4 + q;
    float acc = 0.f;
    #pragma unroll 4
    for (int d = 0; d < DIM; d++) acc += xr[d] * wr[(size_t)d*16];
    out[idx] = acc;
}

// ---------------- driver ----------------
extern "C" void kernel_launch(void* const* d_in, const int* in_sizes, int n_in,
                              void* d_out, int out_size)
{
    const float* fields   = (const float*)d_in[0];
    const unsigned char* visible = (const unsigned char*)d_in[1];
    const float* z        = (const float*)d_in[2];
    const float* W_in     = (const float*)d_in[3];
    const float* W_out    = (const float*)d_in[4];
    const float* noise_W  = (const float*)d_in[5];
    const float* noise_b  = (const float*)d_in[6];
    const float* mask_emb = (const float*)d_in[7];
    const float* pos_emb  = (const float*)d_in[8];
    const float* ln1_s    = (const float*)d_in[9];
    const float* ln1_b    = (const float*)d_in[10];
    const float* Wqkv     = (const float*)d_in[11];
    const float* bqkv     = (const float*)d_in[12];
    const float* Wo       = (const float*)d_in[13];
    const float* bo       = (const float*)d_in[14];
    const float* ln2_s    = (const float*)d_in[15];
    const float* ln2_b    = (const float*)d_in[16];
    const float* W1       = (const float*)d_in[17];
    const float* b1       = (const float*)d_in[18];
    const float* W2       = (const float*)d_in[19];
    const float* b2       = (const float*)d_in[20];

    float *xp, *hp, *qkvp, *mlpp;
    cudaGetSymbolAddress((void**)&xp,   g_x);
    cudaGetSymbolAddress((void**)&hp,   g_h);
    cudaGetSymbolAddress((void**)&qkvp, g_qkv);
    cudaGetSymbolAddress((void**)&mlpp, g_mlp);

    cudaFuncSetAttribute(attn_fused, cudaFuncAttributeMaxDynamicSharedMemorySize,
                         ATTN_SMEM);

    probe_visible<<<1, 32>>>(visible);
    embed_kernel<<<ROWS, 256>>>(fields, visible, W_in, mask_emb, pos_emb, noise_b, xp);

    gemm3<<<dim3(DIM/128, ROWS/128), 256>>>(z, DIM, noise_W, DIM, xp, DIM,
                                            DIM, nullptr, 2);

    for (int l = 0; l < LAYERS; l++) {
        ln_kernel<<<ROWS, 256>>>(xp, ln1_s + l*DIM, ln1_b + l*DIM, hp);

        gemm3<<<dim3(QKVD/128, ROWS/128), 256>>>(hp, DIM,
                                                 Wqkv + (size_t)l*DIM*QKVD, QKVD,
                                                 qkvp, QKVD,
                                                 DIM, bqkv + (size_t)l*QKVD, 0);

        attn_fused<<<dim3(NTOK/64, BE*NHEADS), 256, ATTN_SMEM>>>(qkvp, hp);

        gemm3<<<dim3(DIM/128, ROWS/128), 256>>>(hp, DIM,
                                                Wo + (size_t)l*DIM*DIM, DIM,
                                                xp, DIM,
                                                DIM, bo + (size_t)l*DIM, 2);

        ln_kernel<<<ROWS, 256>>>(xp, ln2_s + l*DIM, ln2_b + l*DIM, hp);

        gemm3<<<dim3(DMLP/128, ROWS/128), 256>>>(hp, DIM,
                                                 W1 + (size_t)l*DIM*DMLP, DMLP,
                                                 mlpp, DMLP,
                                                 DIM, b1 + (size_t)l*DMLP, 1);

        gemm3<<<dim3(DIM/128, ROWS/128), 256>>>(mlpp, DMLP,
                                                W2 + (size_t)l*DMLP*DIM, DIM,
                                                xp, DIM,
                                                DMLP, b2 + (size_t)l*DIM, 2);
    }

    out_kernel<<<(BATCH*VIEWS*64*128*EMEM)/256, 256>>>(xp, W_out, (float*)d_out);
}